// round 7
// baseline (speedup 1.0000x reference)
#include <cuda_runtime.h>
#include <cstdint>

// ---------------------------------------------------------------------------
// PestDetectionSNN: two-layer LIF SNN. Full fp32 (reference is fp32 — the
// tf32 experiment made error 3x worse).
//   Z = event[25600,1024] @ W1[1024,128]   (pass 1: fp32x2 GEMM, 2-level acc)
//   per-batch LIF scans + spike dots + classifier scan (pass 2)
//
// Accuracy strategy: spike thresholds amplify any Z deviation (1 flip ~ 6e-3
// rel_err). We can't bit-match the unknown reference accumulation order, so
// we minimize OUR distance to the true sum: 16-term FMA chains per k-block,
// block sums folded into a running total (2-level accumulation, sigma~2.2e-7
// vs 7.8e-7 for a flat 1024-term chain). Band vs a blocked fp32 reference
// ~3.6e-7 -> expected spike flips ~0.14.
// ---------------------------------------------------------------------------

#define B_  256
#define T_  100
#define D_  1024
#define H_  128
#define C_  5
#define MT  (B_ * T_)          // 25600 GEMM rows

// LIF decay constants (float32 round of np.exp(-1/10), np.exp(-1/20))
#define DECAY1 0.90483741803595952865f
#define DECAY2 0.95122942450071400910f

// Scratch: Z = x @ W1, [25600 x 128] fp32 (13.1 MB) — static device global.
__device__ float g_Z[MT * H_];

// ---- packed fp32x2 helpers (Blackwell FFMA2/FADD2 path) -------------------
__device__ __forceinline__ unsigned long long pack2(float x) {
    unsigned long long r;
    unsigned u = __float_as_uint(x);
    asm("mov.b64 %0, {%1, %1};" : "=l"(r) : "r"(u));
    return r;
}
__device__ __forceinline__ void fma2(unsigned long long& d,
                                     unsigned long long a,
                                     unsigned long long b,
                                     unsigned long long c) {
    asm("fma.rn.f32x2 %0, %1, %2, %3;" : "=l"(d) : "l"(a), "l"(b), "l"(c));
}
__device__ __forceinline__ void add2(unsigned long long& d,
                                     unsigned long long a,
                                     unsigned long long b) {
    asm("add.rn.f32x2 %0, %1, %2;" : "=l"(d) : "l"(a), "l"(b));
}
__device__ __forceinline__ void unpack2(unsigned long long v, float& lo, float& hi) {
    unsigned a, b;
    asm("mov.b64 {%0, %1}, %2;" : "=r"(a), "=r"(b) : "l"(v));
    lo = __uint_as_float(a);
    hi = __uint_as_float(b);
}

// ---------------------------------------------------------------------------
// Pass 1: GEMM  Z[25600,128] = A[25600,1024] @ W1[1024,128]
// BM=64, BN=128, BK=16, 256 threads, per-thread 4x8 microtile.
// Per k-block: fresh 16-term fp32x2 FMA chain (accB); folded into running
// total (accT) with one packed add -> 2-level accumulation.
// ---------------------------------------------------------------------------
__global__ __launch_bounds__(256) void snn_gemm_kernel(
    const float* __restrict__ A, const float* __restrict__ W1)
{
    __shared__ float As[2][16][64];    // transposed: As[k][m]
    __shared__ float Bs[2][16][128];   // Bs[k][n]

    const int tid = threadIdx.x;
    const int m0  = blockIdx.x * 64;

    // A load map: 64 rows x 4 float4-cols -> 1 float4 / thread
    const int ar = tid >> 2;            // 0..63
    const int ac = (tid & 3) << 2;      // 0,4,8,12
    // B load map: 16 rows x 32 float4-cols -> 2 float4 / thread
    const int br = tid >> 5;            // 0..7  (+8 for second load)
    const int bc = (tid & 31) << 2;     // 0..124
    // compute map
    const int tx = tid & 15;            // n = tx*8
    const int ty = tid >> 4;            // m = ty*4

    const float* Aptr = A  + (size_t)(m0 + ar) * D_ + ac;
    const float* Bptr = W1 + br * H_ + bc;

    // prologue: k-block 0 into buffer 0
    float4 aR  = *(const float4*)(Aptr);
    float4 bR0 = *(const float4*)(Bptr);
    float4 bR1 = *(const float4*)(Bptr + 8 * H_);

    As[0][ac + 0][ar] = aR.x;
    As[0][ac + 1][ar] = aR.y;
    As[0][ac + 2][ar] = aR.z;
    As[0][ac + 3][ar] = aR.w;
    *(float4*)&Bs[0][br][bc]     = bR0;
    *(float4*)&Bs[0][br + 8][bc] = bR1;
    __syncthreads();

    unsigned long long accT[4][4];   // running total (level 2)
#pragma unroll
    for (int m = 0; m < 4; m++)
#pragma unroll
        for (int n = 0; n < 4; n++) accT[m][n] = 0ull;

    int buf = 0;
    const int NKB = D_ / 16;  // 64
    for (int kb = 0; kb < NKB; kb++) {
        if (kb < NKB - 1) {
            const float* Ap = Aptr + (kb + 1) * 16;
            const float* Bp = Bptr + (size_t)(kb + 1) * 16 * H_;
            aR  = *(const float4*)(Ap);
            bR0 = *(const float4*)(Bp);
            bR1 = *(const float4*)(Bp + 8 * H_);
        }

        unsigned long long accB[4][4];   // per-block chain (level 1)
#pragma unroll
        for (int m = 0; m < 4; m++)
#pragma unroll
            for (int n = 0; n < 4; n++) accB[m][n] = 0ull;

#pragma unroll
        for (int k = 0; k < 16; k++) {
            float4 av = *(const float4*)&As[buf][k][ty << 2];
            ulonglong2 bv0 = *(const ulonglong2*)&Bs[buf][k][tx << 3];
            ulonglong2 bv1 = *(const ulonglong2*)&Bs[buf][k][(tx << 3) + 4];

            unsigned long long a2[4];
            a2[0] = pack2(av.x); a2[1] = pack2(av.y);
            a2[2] = pack2(av.z); a2[3] = pack2(av.w);
            unsigned long long bp[4] = { bv0.x, bv0.y, bv1.x, bv1.y };

#pragma unroll
            for (int m = 0; m < 4; m++)
#pragma unroll
                for (int n = 0; n < 4; n++)
                    fma2(accB[m][n], a2[m], bp[n], accB[m][n]);
        }

        // fold block sum into running total
#pragma unroll
        for (int m = 0; m < 4; m++)
#pragma unroll
            for (int n = 0; n < 4; n++)
                add2(accT[m][n], accT[m][n], accB[m][n]);

        if (kb < NKB - 1) {
            const int nb = buf ^ 1;
            As[nb][ac + 0][ar] = aR.x;
            As[nb][ac + 1][ar] = aR.y;
            As[nb][ac + 2][ar] = aR.z;
            As[nb][ac + 3][ar] = aR.w;
            *(float4*)&Bs[nb][br][bc]     = bR0;
            *(float4*)&Bs[nb][br + 8][bc] = bR1;
            __syncthreads();
            buf = nb;
        }
    }

    // epilogue: write 4x8 tile
    float* Zp = g_Z + (size_t)(m0 + (ty << 2)) * H_ + (tx << 3);
#pragma unroll
    for (int m = 0; m < 4; m++) {
        float f0, f1, f2, f3, f4, f5, f6, f7;
        unpack2(accT[m][0], f0, f1);
        unpack2(accT[m][1], f2, f3);
        unpack2(accT[m][2], f4, f5);
        unpack2(accT[m][3], f6, f7);
        float4 o0 = make_float4(f0, f1, f2, f3);
        float4 o1 = make_float4(f4, f5, f6, f7);
        *(float4*)(Zp + m * H_)     = o0;
        *(float4*)(Zp + m * H_ + 4) = o1;
    }
}

// ---------------------------------------------------------------------------
// Pass 2: per-batch LIF scans.
//   phase 1: thread h scans v1 over t; spikes packed via ballot into smem bits
//   phase 2: 500 (t,c) dot products of spike-bitmask rows with W2 columns
//   phase 3: threads 0..4 run the classifier LIF scan and write out
// ---------------------------------------------------------------------------
__global__ __launch_bounds__(128) void snn_scan_kernel(
    const float* __restrict__ b1, const float* __restrict__ W2,
    const float* __restrict__ b2, float* __restrict__ out)
{
    __shared__ unsigned s1w[T_ * 4];     // spike bitmasks: [t][warp]
    __shared__ float    W2s[H_ * C_];    // 640 floats
    __shared__ float    dd[T_ * C_];     // layer-2 drive per (t,c)

    const int b   = blockIdx.x;
    const int tid = threadIdx.x;         // = h
    const int lane = tid & 31;
    const int warp = tid >> 5;

    for (int i = tid; i < H_ * C_; i += 128) W2s[i] = W2[i];

    // ---- phase 1: feature-layer LIF scan ----
    const float b1h = b1[tid];
    const float* zp = g_Z + (size_t)b * T_ * H_ + tid;
    float v1 = 0.0f;
#pragma unroll 4
    for (int t = 0; t < T_; t++) {
        float z = zp[t * H_];
        // fma(v1, decay, z) + b1 — LLVM-contracted form on both XLA backends
        v1 = __fadd_rn(fmaf(v1, DECAY1, z), b1h);
        bool s = (v1 >= 1.0f);
        if (s) v1 = 0.0f;
        unsigned m = __ballot_sync(0xffffffffu, s);
        if (lane == 0) s1w[t * 4 + warp] = m;
    }
    __syncthreads();

    // ---- phase 2: s1 @ W2 for all (t,c) ----
    // (adding only nonzero terms: skipped zeros are exact, order = ascending h)
    for (int p = tid; p < T_ * C_; p += 128) {
        const int t = p / C_;
        const int c = p - t * C_;
        float sum = 0.0f;
#pragma unroll
        for (int w = 0; w < 4; w++) {
            const unsigned msk = s1w[t * 4 + w];
            const float* wp = &W2s[w * 32 * C_ + c];
#pragma unroll
            for (int bit = 0; bit < 32; bit++) {
                if (msk & (1u << bit)) sum = __fadd_rn(sum, wp[bit * C_]);
            }
        }
        dd[p] = sum;
    }
    __syncthreads();

    // ---- phase 3: classifier LIF scan ----
    if (tid < C_) {
        const float b2c = b2[tid];
        float v2 = 0.0f, acc = 0.0f;
        for (int t = 0; t < T_; t++) {
            v2 = __fadd_rn(fmaf(v2, DECAY2, dd[t * C_ + tid]), b2c);
            if (v2 >= 1.0f) { acc += 1.0f; v2 = 0.0f; }
        }
        out[b * C_ + tid] = acc / (float)T_;
    }
}

// ---------------------------------------------------------------------------
// kernel_launch
// inputs: event_stream[256,100,1024] f32, W1[1024,128], b1[128], W2[128,5], b2[5]
// output: [256,5] f32
// ---------------------------------------------------------------------------
extern "C" void kernel_launch(void* const* d_in, const int* in_sizes, int n_in,
                              void* d_out, int out_size)
{
    const float* ev = (const float*)d_in[0];
    const float* W1 = (const float*)d_in[1];
    const float* b1 = (const float*)d_in[2];
    const float* W2 = (const float*)d_in[3];
    const float* b2 = (const float*)d_in[4];
    float* out = (float*)d_out;

    snn_gemm_kernel<<<MT / 64, 256>>>(ev, W1);
    snn_scan_kernel<<<B_, 128>>>(b1, W2, b2, out);
}

// round 9
// speedup vs baseline: 1.3173x; 1.3173x over previous
#include <cuda_runtime.h>
#include <cstdint>

// ---------------------------------------------------------------------------
// PestDetectionSNN: two-layer LIF SNN, full fp32.
//   Pass 1: Z = event[25600,1024] @ W1[1024,128]  (fp32x2 GEMM, 2-level acc)
//   Pass 2: per-batch LIF scans + spike dots + classifier scan
//
// Numerics (must not change — R7 passed at 4.1e-8): per output, 64 blocks of
// 16-term FMA chains in ascending k, block sums folded into a running total.
// R9 fix: As row padding 66 -> 68 floats (272B = 16B-aligned rows; the 66
// padding made odd-k float4 LDS misaligned -> HW trap).
// ---------------------------------------------------------------------------

#define B_  256
#define T_  100
#define D_  1024
#define H_  128
#define C_  5
#define MT  (B_ * T_)          // 25600 GEMM rows

#define DECAY1 0.90483741803595952865f
#define DECAY2 0.95122942450071400910f

// Scratch: Z = x @ W1, [25600 x 128] fp32 (13.1 MB)
__device__ float g_Z[MT * H_];

// ---- packed fp32x2 helpers (Blackwell FFMA2/FADD2 path) -------------------
__device__ __forceinline__ unsigned long long pack2(float x) {
    unsigned long long r;
    unsigned u = __float_as_uint(x);
    asm("mov.b64 %0, {%1, %1};" : "=l"(r) : "r"(u));
    return r;
}
__device__ __forceinline__ void fma2(unsigned long long& d,
                                     unsigned long long a,
                                     unsigned long long b,
                                     unsigned long long c) {
    asm("fma.rn.f32x2 %0, %1, %2, %3;" : "=l"(d) : "l"(a), "l"(b), "l"(c));
}
__device__ __forceinline__ void add2(unsigned long long& d,
                                     unsigned long long a,
                                     unsigned long long b) {
    asm("add.rn.f32x2 %0, %1, %2;" : "=l"(d) : "l"(a), "l"(b));
}
__device__ __forceinline__ void unpack2(unsigned long long v, float& lo, float& hi) {
    unsigned a, b;
    asm("mov.b64 {%0, %1}, %2;" : "=r"(a), "=r"(b) : "l"(v));
    lo = __uint_as_float(a);
    hi = __uint_as_float(b);
}

// ---------------------------------------------------------------------------
// Pass 1: GEMM  Z[25600,128] = A[25600,1024] @ W1[1024,128]
// BM=64, BN=64, BK=16, 256 threads, 4x4 microtile, double-buffered smem.
// Grid = 400 M-tiles x 2 N-tiles = 800 CTAs; target 3 CTAs/SM.
// ---------------------------------------------------------------------------
__global__ __launch_bounds__(256, 3) void snn_gemm_kernel(
    const float* __restrict__ A, const float* __restrict__ W1)
{
    // 68-float rows: 272B per row -> every row base 16B-aligned for float4 LDS
    __shared__ float As[2][16][68];    // transposed A: As[k][m]
    __shared__ float Bs[2][16][64];    // Bs[k][n]

    const int tid = threadIdx.x;
    const int bx  = blockIdx.x;
    const int m0  = (bx >> 1) * 64;
    const int n0  = (bx & 1) * 64;

    // A load map: 64 rows x 4 float4-cols -> 1 float4 / thread
    const int ar = tid >> 2;            // 0..63
    const int ac = (tid & 3) << 2;      // 0,4,8,12
    // B load map: 16 rows x 16 float4-cols -> 1 float4 / thread
    const int br = tid >> 4;            // 0..15
    const int bc = (tid & 15) << 2;     // 0..60
    // compute map: 16x16 threads, each owns 4 (M) x 4 (N)
    const int tx = tid & 15;            // n = tx*4
    const int ty = tid >> 4;            // m = ty*4

    const float* Aptr = A  + (size_t)(m0 + ar) * D_ + ac;
    const float* Bptr = W1 + br * H_ + n0 + bc;

    // prologue: k-block 0 into buffer 0
    float4 aR = *(const float4*)(Aptr);
    float4 bR = *(const float4*)(Bptr);

    As[0][ac + 0][ar] = aR.x;
    As[0][ac + 1][ar] = aR.y;
    As[0][ac + 2][ar] = aR.z;
    As[0][ac + 3][ar] = aR.w;
    *(float4*)&Bs[0][br][bc] = bR;
    __syncthreads();

    unsigned long long accT[4][2];   // running totals (level 2): 4 M x 2 pairs
#pragma unroll
    for (int m = 0; m < 4; m++) { accT[m][0] = 0ull; accT[m][1] = 0ull; }

    int buf = 0;
    const int NKB = D_ / 16;  // 64
    for (int kb = 0; kb < NKB; kb++) {
        if (kb < NKB - 1) {
            aR = *(const float4*)(Aptr + (kb + 1) * 16);
            bR = *(const float4*)(Bptr + (size_t)(kb + 1) * 16 * H_);
        }

        unsigned long long accB[4][2];   // per-block 16-term chains (level 1)
#pragma unroll
        for (int m = 0; m < 4; m++) { accB[m][0] = 0ull; accB[m][1] = 0ull; }

#pragma unroll
        for (int k = 0; k < 16; k++) {
            float4 av = *(const float4*)&As[buf][k][ty << 2];
            ulonglong2 bv = *(const ulonglong2*)&Bs[buf][k][tx << 2];

            unsigned long long a2[4];
            a2[0] = pack2(av.x); a2[1] = pack2(av.y);
            a2[2] = pack2(av.z); a2[3] = pack2(av.w);

#pragma unroll
            for (int m = 0; m < 4; m++) {
                fma2(accB[m][0], a2[m], bv.x, accB[m][0]);
                fma2(accB[m][1], a2[m], bv.y, accB[m][1]);
            }
        }

        // fold block sums into running totals
#pragma unroll
        for (int m = 0; m < 4; m++) {
            add2(accT[m][0], accT[m][0], accB[m][0]);
            add2(accT[m][1], accT[m][1], accB[m][1]);
        }

        if (kb < NKB - 1) {
            const int nb = buf ^ 1;
            As[nb][ac + 0][ar] = aR.x;
            As[nb][ac + 1][ar] = aR.y;
            As[nb][ac + 2][ar] = aR.z;
            As[nb][ac + 3][ar] = aR.w;
            *(float4*)&Bs[nb][br][bc] = bR;
            __syncthreads();
            buf = nb;
        }
    }

    // epilogue: write 4x4 tile (one float4 per M-row)
    float* Zp = g_Z + (size_t)(m0 + (ty << 2)) * H_ + n0 + (tx << 2);
#pragma unroll
    for (int m = 0; m < 4; m++) {
        float f0, f1, f2, f3;
        unpack2(accT[m][0], f0, f1);
        unpack2(accT[m][1], f2, f3);
        *(float4*)(Zp + m * H_) = make_float4(f0, f1, f2, f3);
    }
}

// ---------------------------------------------------------------------------
// Pass 2: per-batch LIF scans.
//   phase 1: thread h scans v1 over t with a 10-deep load prefetch pipeline;
//            spikes packed via ballot into smem bitmasks
//   phase 2: 500 (t,c) dot products of spike bitmasks with W2 columns
//   phase 3: threads 0..4 run the classifier LIF scan and write out
// ---------------------------------------------------------------------------
__global__ __launch_bounds__(128) void snn_scan_kernel(
    const float* __restrict__ b1, const float* __restrict__ W2,
    const float* __restrict__ b2, float* __restrict__ out)
{
    __shared__ unsigned s1w[T_ * 4];     // spike bitmasks: [t][warp]
    __shared__ float    W2s[H_ * C_];    // 640 floats
    __shared__ float    dd[T_ * C_];     // layer-2 drive per (t,c)

    const int b    = blockIdx.x;
    const int tid  = threadIdx.x;        // = h
    const int lane = tid & 31;
    const int warp = tid >> 5;

    for (int i = tid; i < H_ * C_; i += 128) W2s[i] = W2[i];

    // ---- phase 1: feature-layer LIF scan (chunked, MLP=10) ----
    const float b1h = b1[tid];
    const float* zp = g_Z + (size_t)b * T_ * H_ + tid;
    float v1 = 0.0f;

    float zbuf[10];
#pragma unroll
    for (int j = 0; j < 10; j++) zbuf[j] = zp[j * H_];

    for (int c = 0; c < 10; c++) {
        float znext[10];
        if (c < 9) {
#pragma unroll
            for (int j = 0; j < 10; j++)
                znext[j] = zp[(c * 10 + 10 + j) * H_];
        }
#pragma unroll
        for (int j = 0; j < 10; j++) {
            const int t = c * 10 + j;
            v1 = __fadd_rn(fmaf(v1, DECAY1, zbuf[j]), b1h);
            bool s = (v1 >= 1.0f);
            if (s) v1 = 0.0f;
            unsigned m = __ballot_sync(0xffffffffu, s);
            if (lane == 0) s1w[t * 4 + warp] = m;
        }
        if (c < 9) {
#pragma unroll
            for (int j = 0; j < 10; j++) zbuf[j] = znext[j];
        }
    }
    __syncthreads();

    // ---- phase 2: s1 @ W2 for all (t,c) ----
    for (int p = tid; p < T_ * C_; p += 128) {
        const int t = p / C_;
        const int c = p - t * C_;
        float sum = 0.0f;
#pragma unroll
        for (int w = 0; w < 4; w++) {
            const unsigned msk = s1w[t * 4 + w];
            const float* wp = &W2s[w * 32 * C_ + c];
#pragma unroll
            for (int bit = 0; bit < 32; bit++) {
                if (msk & (1u << bit)) sum = __fadd_rn(sum, wp[bit * C_]);
            }
        }
        dd[p] = sum;
    }
    __syncthreads();

    // ---- phase 3: classifier LIF scan ----
    if (tid < C_) {
        const float b2c = b2[tid];
        float v2 = 0.0f, acc = 0.0f;
        for (int t = 0; t < T_; t++) {
            v2 = __fadd_rn(fmaf(v2, DECAY2, dd[t * C_ + tid]), b2c);
            if (v2 >= 1.0f) { acc += 1.0f; v2 = 0.0f; }
        }
        out[b * C_ + tid] = acc / (float)T_;
    }
}

// ---------------------------------------------------------------------------
// kernel_launch
// inputs: event_stream[256,100,1024] f32, W1[1024,128], b1[128], W2[128,5], b2[5]
// output: [256,5] f32
// ---------------------------------------------------------------------------
extern "C" void kernel_launch(void* const* d_in, const int* in_sizes, int n_in,
                              void* d_out, int out_size)
{
    const float* ev = (const float*)d_in[0];
    const float* W1 = (const float*)d_in[1];
    const float* b1 = (const float*)d_in[2];
    const float* W2 = (const float*)d_in[3];
    const float* b2 = (const float*)d_in[4];
    float* out = (float*)d_out;

    snn_gemm_kernel<<<(MT / 64) * 2, 256>>>(ev, W1);
    snn_scan_kernel<<<B_, 128>>>(b1, W2, b2, out);
}